// round 10
// baseline (speedup 1.0000x reference)
#include <cuda_runtime.h>
#define TPB 512
typedef unsigned long long ull;

static __device__ __forceinline__ ull pk(float lo, float hi){ ull r; asm("mov.b64 %0,{%1,%2};":"=l"(r):"f"(lo),"f"(hi)); return r; }
static __device__ __forceinline__ void upk(ull v, float &lo, float &hi){ asm("mov.b64 {%0,%1},%2;":"=f"(lo),"=f"(hi):"l"(v)); }
static __device__ __forceinline__ void fma2(ull &d, ull a, ull b){ asm("fma.rn.f32x2 %0,%1,%2,%0;":"+l"(d):"l"(a),"l"(b)); }
static __device__ __forceinline__ float siluf(float z){ return z*(1.f/(1.f+__expf(-z))); }
static __device__ __forceinline__ float dsiluf(float z){ float s=1.f/(1.f+__expf(-z)); return s*(1.f+z*(1.f-s)); }

__device__ float g_cd[2][256];

// XOR-16B-chunk swizzle for [col][row] buffers (32 rows = 8 chunks of 4 floats)
#define CHK(c, r0) ((((r0) >> 2) ^ ((c) & 7)) << 2)
#define SWI(c, r)  ((c)*32 + CHK(c, r) + ((r) & 3))

// ---- SMEM float offsets ----
#define O_BASE 0
#define O_TZ1  8192
#define O_WE   16384
#define O_POOL 24576     // 32768
#define O_DR   57344
#define O_PB   57376     // 128
#define SMEM_FLOATS 57504
// pool-relative
#define P_A12  0         // 3*8192 (primal); JVP quad 4*8192; OUT3 3*4096 overlay
#define P_CND  24576     // 1536
#define P_Y    26112     // 2048 (phase-1 temp)
#define P_EPS  28160     // 2048 (phase-1 temp)
#define P_W3T  0         // 16640 (phase-1 temp, under A12)

__global__ void precompute_k(const float* __restrict__ cu, const float* __restrict__ cv,
                             const float* __restrict__ W1){
    int c = threadIdx.x;
    float su = 0.f, sv = 0.f;
    #pragma unroll
    for (int j = 0; j < 16; j++){
        float w = __ldg(W1 + (65+j)*256 + c);
        su += __ldg(cu + j) * w;
        sv += __ldg(cv + j) * w;
    }
    g_cd[0][c] = su; g_cd[1][c] = sv;
}

__global__ void __launch_bounds__(TPB, 1) node_main(
    const float* __restrict__ gt, const float* __restrict__ gx, const float* __restrict__ geps,
    const float* __restrict__ gcu, const float* __restrict__ gcv, const float* __restrict__ gcf,
    const float* __restrict__ W1, const float* __restrict__ b1,
    const float* __restrict__ W2, const float* __restrict__ b2,
    const float* __restrict__ W3, const float* __restrict__ b3,
    float* __restrict__ out, int B)
{
    extern __shared__ float sm[];
    const int tid  = threadIdx.x;
    const int lane = tid & 31;
    const int wp   = tid >> 5;
    const int row0 = blockIdx.x * 32;

    // ---- P0 ----
    for (int i = tid; i < 64*32; i += TPB){
        int r = i & 31, d = i >> 5; int gr = row0 + r;
        sm[O_POOL + P_Y   + SWI(d, r)] = (gr < B) ? gx[(size_t)gr*65 + d]  : 0.f;
        sm[O_POOL + P_EPS + SWI(d, r)] = (gr < B) ? geps[(size_t)gr*64 + d] : 0.f;
    }
    for (int i = tid; i < 3*16*32; i += TPB){
        int r = i & 31, j = (i >> 5) & 15, s = i >> 9;
        int gr = row0 + r; int gi = (gr < B) ? gr : 0;
        const float* src = (s == 0) ? gcf : ((s == 1) ? gcu : gcv);
        sm[O_POOL + P_CND + s*512 + SWI(j, r)] = src[(size_t)gi*16 + j];
    }
    for (int i = tid; i < 256*64; i += TPB){
        int k = i >> 6, j = i & 63;
        sm[O_POOL + P_W3T + j*260 + k] = __ldg(W3 + k*128 + j);
    }
    __syncthreads();

    // ---- fillBase (warps 0-7) + WE (warps 8-15) ----
    if (wp < 8){
        int s = wp >> 2, cb = (wp >> 1) & 1, rb = wp & 1;
        int c0 = cb*128 + lane, r0 = rb*16;
        ull acc[8][4];
        #pragma unroll
        for (int i = 0; i < 8; i++){ acc[i][0]=0; acc[i][1]=0; acc[i][2]=0; acc[i][3]=0; }
        const float* act = sm + O_POOL + (s ? P_EPS : P_Y);
        #pragma unroll 4
        for (int k = 0; k < 64; k++){
            float w0 = __ldg(W1 + k*256 + c0),      w1 = __ldg(W1 + k*256 + c0 + 32);
            float w2 = __ldg(W1 + k*256 + c0 + 64), w3 = __ldg(W1 + k*256 + c0 + 96);
            ull wd[4] = {pk(w0,w0), pk(w1,w1), pk(w2,w2), pk(w3,w3)};
            ulonglong2 q0 = *(const ulonglong2*)(act + k*32 + CHK(k, r0));
            ulonglong2 q1 = *(const ulonglong2*)(act + k*32 + CHK(k, r0+4));
            ulonglong2 q2 = *(const ulonglong2*)(act + k*32 + CHK(k, r0+8));
            ulonglong2 q3 = *(const ulonglong2*)(act + k*32 + CHK(k, r0+12));
            ull ar[8] = {q0.x,q0.y,q1.x,q1.y,q2.x,q2.y,q3.x,q3.y};
            #pragma unroll
            for (int rp = 0; rp < 8; rp++)
                #pragma unroll
                for (int j = 0; j < 4; j++) fma2(acc[rp][j], ar[rp], wd[j]);
        }
        float tv = __ldg(gt);
        #pragma unroll
        for (int j = 0; j < 4; j++){
            int c = c0 + 32*j;
            float sft = (s == 0) ? (tv*__ldg(W1 + 64*256 + c) + __ldg(b1 + c)) : 0.f;
            int obuf = (s == 0) ? O_BASE : O_TZ1;
            #pragma unroll
            for (int rp = 0; rp < 8; rp++){
                int r = r0 + 2*rp;
                float lo, hi; upk(acc[rp][j], lo, hi);
                *(float2*)(sm + obuf + c*32 + CHK(c, r) + (r & 3)) = make_float2(lo + sft, hi + sft);
            }
        }
    } else {
        int w8 = wp - 8; int kb = (w8 >> 1)*64 + lane, rb = w8 & 1, r0 = rb*16;
        ull acc[8][2];
        #pragma unroll
        for (int i = 0; i < 8; i++){ acc[i][0]=0; acc[i][1]=0; }
        const float* act = sm + O_POOL + P_EPS;
        #pragma unroll 4
        for (int c = 0; c < 64; c++){
            float w0 = sm[O_POOL + P_W3T + c*260 + kb];
            float w1 = sm[O_POOL + P_W3T + c*260 + kb + 32];
            ull wd[2] = {pk(w0,w0), pk(w1,w1)};
            ulonglong2 q0 = *(const ulonglong2*)(act + c*32 + CHK(c, r0));
            ulonglong2 q1 = *(const ulonglong2*)(act + c*32 + CHK(c, r0+4));
            ulonglong2 q2 = *(const ulonglong2*)(act + c*32 + CHK(c, r0+8));
            ulonglong2 q3 = *(const ulonglong2*)(act + c*32 + CHK(c, r0+12));
            ull ar[8] = {q0.x,q0.y,q1.x,q1.y,q2.x,q2.y,q3.x,q3.y};
            #pragma unroll
            for (int rp = 0; rp < 8; rp++){
                fma2(acc[rp][0], ar[rp], wd[0]);
                fma2(acc[rp][1], ar[rp], wd[1]);
            }
        }
        #pragma unroll
        for (int j = 0; j < 2; j++){
            int k = kb + 32*j;
            #pragma unroll
            for (int rp = 0; rp < 8; rp++){
                int r = r0 + 2*rp;
                float lo, hi; upk(acc[rp][j], lo, hi);
                *(float2*)(sm + O_WE + k*32 + CHK(k, r) + (r & 3)) = make_float2(lo, hi);
            }
        }
    }
    __syncthreads();

    const int sA = wp >> 2, cbA = (wp >> 1) & 1, rbA = wp & 1;
    const int c0A = cbA*128 + lane, r0A = rbA*16;

    // ---- fillA1 (3 conds, K=16) ----
    if (wp < 12){
        ull acc[8][4];
        #pragma unroll
        for (int i = 0; i < 8; i++){ acc[i][0]=0; acc[i][1]=0; acc[i][2]=0; acc[i][3]=0; }
        const float* act = sm + O_POOL + P_CND + sA*512;
        #pragma unroll
        for (int k = 0; k < 16; k++){
            const float* wr = W1 + (65+k)*256 + c0A;
            float w0 = __ldg(wr), w1 = __ldg(wr+32), w2 = __ldg(wr+64), w3 = __ldg(wr+96);
            ull wd[4] = {pk(w0,w0), pk(w1,w1), pk(w2,w2), pk(w3,w3)};
            ulonglong2 q0 = *(const ulonglong2*)(act + k*32 + CHK(k, r0A));
            ulonglong2 q1 = *(const ulonglong2*)(act + k*32 + CHK(k, r0A+4));
            ulonglong2 q2 = *(const ulonglong2*)(act + k*32 + CHK(k, r0A+8));
            ulonglong2 q3 = *(const ulonglong2*)(act + k*32 + CHK(k, r0A+12));
            ull ar[8] = {q0.x,q0.y,q1.x,q1.y,q2.x,q2.y,q3.x,q3.y};
            #pragma unroll
            for (int rp = 0; rp < 8; rp++)
                #pragma unroll
                for (int j = 0; j < 4; j++) fma2(acc[rp][j], ar[rp], wd[j]);
        }
        #pragma unroll
        for (int j = 0; j < 4; j++){
            int c = c0A + 32*j;
            #pragma unroll
            for (int rp = 0; rp < 8; rp++){
                int r = r0A + 2*rp;
                float lo, hi; upk(acc[rp][j], lo, hi);
                float2 b = *(const float2*)(sm + O_BASE + c*32 + CHK(c, r) + (r & 3));
                *(float2*)(sm + O_POOL + P_A12 + sA*8192 + c*32 + CHK(c, r) + (r & 3)) =
                    make_float2(siluf(lo + b.x), siluf(hi + b.y));
            }
        }
    }
    __syncthreads();

    // ---- layer2 primal (in-place A12, direct LDG W2) ----
    {
        ull acc[8][4];
        #pragma unroll
        for (int i = 0; i < 8; i++){ acc[i][0]=0; acc[i][1]=0; acc[i][2]=0; acc[i][3]=0; }
        if (wp < 12){
            const float* act = sm + O_POOL + P_A12 + sA*8192;
            #pragma unroll 4
            for (int k = 0; k < 256; k++){
                const float* wr = W2 + k*256 + c0A;
                float w0 = __ldg(wr), w1 = __ldg(wr+32), w2 = __ldg(wr+64), w3 = __ldg(wr+96);
                ull wd[4] = {pk(w0,w0), pk(w1,w1), pk(w2,w2), pk(w3,w3)};
                ulonglong2 q0 = *(const ulonglong2*)(act + k*32 + CHK(k, r0A));
                ulonglong2 q1 = *(const ulonglong2*)(act + k*32 + CHK(k, r0A+4));
                ulonglong2 q2 = *(const ulonglong2*)(act + k*32 + CHK(k, r0A+8));
                ulonglong2 q3 = *(const ulonglong2*)(act + k*32 + CHK(k, r0A+12));
                ull ar[8] = {q0.x,q0.y,q1.x,q1.y,q2.x,q2.y,q3.x,q3.y};
                #pragma unroll
                for (int rp = 0; rp < 8; rp++)
                    #pragma unroll
                    for (int j = 0; j < 4; j++) fma2(acc[rp][j], ar[rp], wd[j]);
            }
        }
        __syncthreads();   // all k-loop reads complete before in-place writes
        if (wp < 12){
            #pragma unroll
            for (int j = 0; j < 4; j++){
                int c = c0A + 32*j;
                float bb = __ldg(b2 + c);
                #pragma unroll
                for (int rp = 0; rp < 8; rp++){
                    int r = r0A + 2*rp;
                    float lo, hi; upk(acc[rp][j], lo, hi);
                    *(float2*)(sm + O_POOL + P_A12 + sA*8192 + c*32 + CHK(c, r) + (r & 3)) =
                        make_float2(siluf(lo + bb), siluf(hi + bb));
                }
            }
        }
    }
    __syncthreads();

    // ---- layer3 primal (128 cols) -> OUT3 overlay ----
    {
        ull acc[8][2];
        #pragma unroll
        for (int i = 0; i < 8; i++){ acc[i][0]=0; acc[i][1]=0; }
        int c03 = cbA*64 + lane;
        if (wp < 12){
            const float* act = sm + O_POOL + P_A12 + sA*8192;
            #pragma unroll 4
            for (int k = 0; k < 256; k++){
                float w0 = __ldg(W3 + k*128 + c03), w1 = __ldg(W3 + k*128 + c03 + 32);
                ull wd[2] = {pk(w0,w0), pk(w1,w1)};
                ulonglong2 q0 = *(const ulonglong2*)(act + k*32 + CHK(k, r0A));
                ulonglong2 q1 = *(const ulonglong2*)(act + k*32 + CHK(k, r0A+4));
                ulonglong2 q2 = *(const ulonglong2*)(act + k*32 + CHK(k, r0A+8));
                ulonglong2 q3 = *(const ulonglong2*)(act + k*32 + CHK(k, r0A+12));
                ull ar[8] = {q0.x,q0.y,q1.x,q1.y,q2.x,q2.y,q3.x,q3.y};
                #pragma unroll
                for (int rp = 0; rp < 8; rp++){
                    fma2(acc[rp][0], ar[rp], wd[0]);
                    fma2(acc[rp][1], ar[rp], wd[1]);
                }
            }
        }
        __syncthreads();   // OUT3 overlays A12 — all reads must complete first
        if (wp < 12){
            #pragma unroll
            for (int j = 0; j < 2; j++){
                int c = c03 + 32*j;
                float bb = __ldg(b3 + c);
                #pragma unroll
                for (int rp = 0; rp < 8; rp++){
                    int r = r0A + 2*rp;
                    float lo, hi; upk(acc[rp][j], lo, hi);
                    *(float2*)(sm + O_POOL + sA*4096 + c*32 + CHK(c, r) + (r & 3)) =
                        make_float2(lo + bb, hi + bb);
                }
            }
        }
    }
    __syncthreads();

    // ---- ft output + corrections ----
    {
        int cc = tid & 15, r = tid >> 4;
        int gr = row0 + r;
        float part = 0.f;
        #pragma unroll
        for (int j = 0; j < 4; j++){
            int c = cc + 16*j;
            float fv = sm[O_POOL + 0*4096 + SWI(c, r)];
            float uv = sm[O_POOL + 1*4096 + SWI(c, r)];
            float vv = sm[O_POOL + 2*4096 + SWI(c, r)];
            float su = sm[O_POOL + 1*4096 + SWI(c + 64, r)];
            float sv = sm[O_POOL + 2*4096 + SWI(c + 64, r)];
            part += (fv - uv)*su - (fv - vv)*sv;
            if (gr < B) out[(size_t)gr*65 + c] = fv;
        }
        part += __shfl_down_sync(0xffffffffu, part, 8, 16);
        part += __shfl_down_sync(0xffffffffu, part, 4, 16);
        part += __shfl_down_sync(0xffffffffu, part, 2, 16);
        part += __shfl_down_sync(0xffffffffu, part, 1, 16);
        if ((tid & 15) == 0) sm[O_DR + r] = part;
    }
    __syncthreads();

    // ---- fillJ: quad streams {pu, tu, pv, tv} ----
    #pragma unroll 4
    for (int ci = 0; ci < 16; ci++){
        int c = wp*16 + ci;
        float bs = sm[O_BASE + SWI(c, lane)];
        float tz = sm[O_TZ1  + SWI(c, lane)];
        float zu = bs + g_cd[0][c], zv = bs + g_cd[1][c];
        sm[O_POOL + 0*8192 + SWI(c, lane)] = siluf(zu);
        sm[O_POOL + 1*8192 + SWI(c, lane)] = dsiluf(zu)*tz;
        sm[O_POOL + 2*8192 + SWI(c, lane)] = siluf(zv);
        sm[O_POOL + 3*8192 + SWI(c, lane)] = dsiluf(zv)*tz;
    }
    __syncthreads();

    // ---- JVP layer2 (16 warps) + fused WE-dot epilogue ----
    {
        ull acc[8][4];
        #pragma unroll
        for (int i = 0; i < 8; i++){ acc[i][0]=0; acc[i][1]=0; acc[i][2]=0; acc[i][3]=0; }
        const float* act = sm + O_POOL + sA*8192;
        #pragma unroll 4
        for (int k = 0; k < 256; k++){
            const float* wr = W2 + k*256 + c0A;
            float w0 = __ldg(wr), w1 = __ldg(wr+32), w2 = __ldg(wr+64), w3 = __ldg(wr+96);
            ull wd[4] = {pk(w0,w0), pk(w1,w1), pk(w2,w2), pk(w3,w3)};
            ulonglong2 q0 = *(const ulonglong2*)(act + k*32 + CHK(k, r0A));
            ulonglong2 q1 = *(const ulonglong2*)(act + k*32 + CHK(k, r0A+4));
            ulonglong2 q2 = *(const ulonglong2*)(act + k*32 + CHK(k, r0A+8));
            ulonglong2 q3 = *(const ulonglong2*)(act + k*32 + CHK(k, r0A+12));
            ull ar[8] = {q0.x,q0.y,q1.x,q1.y,q2.x,q2.y,q3.x,q3.y};
            #pragma unroll
            for (int rp = 0; rp < 8; rp++)
                #pragma unroll
                for (int j = 0; j < 4; j++) fma2(acc[rp][j], ar[rp], wd[j]);
        }
        __syncthreads();   // all reads complete before z2 staging overlays
        if ((sA & 1) == 0){
            #pragma unroll
            for (int j = 0; j < 4; j++){
                int c = c0A + 32*j;
                #pragma unroll
                for (int rp = 0; rp < 8; rp++){
                    int r = r0A + 2*rp;
                    float lo, hi; upk(acc[rp][j], lo, hi);
                    *(float2*)(sm + O_POOL + sA*8192 + c*32 + CHK(c, r) + (r & 3)) = make_float2(lo, hi);
                }
            }
        }
        __syncthreads();
        if (sA & 1){
            float prow[16];
            #pragma unroll
            for (int i = 0; i < 16; i++) prow[i] = 0.f;
            #pragma unroll
            for (int j = 0; j < 4; j++){
                int c = c0A + 32*j;
                float bb = __ldg(b2 + c);
                #pragma unroll
                for (int rp = 0; rp < 8; rp++){
                    int r = r0A + 2*rp;
                    float2 z  = *(const float2*)(sm + O_POOL + (sA-1)*8192 + c*32 + CHK(c, r) + (r & 3));
                    float2 we = *(const float2*)(sm + O_WE + c*32 + CHK(c, r) + (r & 3));
                    float t0, t1; upk(acc[rp][j], t0, t1);
                    prow[2*rp]   += dsiluf(z.x + bb) * t0 * we.x;
                    prow[2*rp+1] += dsiluf(z.y + bb) * t1 * we.y;
                }
            }
            #pragma unroll
            for (int off = 16; off >= 1; off >>= 1)
                #pragma unroll
                for (int i = 0; i < 16; i++)
                    prow[i] += __shfl_down_sync(0xffffffffu, prow[i], off);
            if (lane == 0){
                int q = (sA >> 1)*2 + cbA;
                #pragma unroll
                for (int i = 0; i < 16; i++) sm[O_PB + q*32 + r0A + i] = prow[i];
            }
        }
    }
    __syncthreads();

    // ---- finalize: dr = corr - e.(Ju e) + e.(Jv e) ----
    if (tid < 32){
        float dr = sm[O_DR + tid]
                 - (sm[O_PB + tid] + sm[O_PB + 32 + tid])
                 + (sm[O_PB + 64 + tid] + sm[O_PB + 96 + tid]);
        int gr = row0 + tid;
        if (gr < B) out[(size_t)gr*65 + 64] = dr;
    }
}

extern "C" void kernel_launch(void* const* d_in, const int* in_sizes, int n_in,
                              void* d_out, int out_size)
{
    const float* gt  = (const float*)d_in[0];
    const float* gx  = (const float*)d_in[1];
    const float* ge  = (const float*)d_in[2];
    const float* gcu = (const float*)d_in[3];
    const float* gcv = (const float*)d_in[4];
    const float* gcf = (const float*)d_in[5];
    const float* W1  = (const float*)d_in[6];
    const float* b1  = (const float*)d_in[7];
    const float* W2  = (const float*)d_in[8];
    const float* b2  = (const float*)d_in[9];
    const float* W3  = (const float*)d_in[10];
    const float* b3  = (const float*)d_in[11];
    float* out = (float*)d_out;

    int B = in_sizes[1] / 65;
    int grid = (B + 31) / 32;

    cudaFuncSetAttribute(node_main, cudaFuncAttributeMaxDynamicSharedMemorySize, SMEM_FLOATS*4);

    precompute_k<<<1, 256>>>(gcu, gcv, W1);
    node_main<<<grid, TPB, SMEM_FLOATS*4>>>(gt, gx, ge, gcu, gcv, gcf,
                                            W1, b1, W2, b2, W3, b3, out, B);
}

// round 11
// speedup vs baseline: 1.0009x; 1.0009x over previous
#include <cuda_runtime.h>
#define TPB 512
typedef unsigned long long ull;

static __device__ __forceinline__ ull pk(float lo, float hi){ ull r; asm("mov.b64 %0,{%1,%2};":"=l"(r):"f"(lo),"f"(hi)); return r; }
static __device__ __forceinline__ void upk(ull v, float &lo, float &hi){ asm("mov.b64 {%0,%1},%2;":"=f"(lo),"=f"(hi):"l"(v)); }
static __device__ __forceinline__ void fma2(ull &d, ull a, ull b){ asm("fma.rn.f32x2 %0,%1,%2,%0;":"+l"(d):"l"(a),"l"(b)); }
static __device__ __forceinline__ float siluf(float z){ return z*(1.f/(1.f+__expf(-z))); }
static __device__ __forceinline__ float dsiluf(float z){ float s=1.f/(1.f+__expf(-z)); return s*(1.f+z*(1.f-s)); }

__device__ float g_cd[2][256];

// XOR-16B-chunk swizzle for [col][row] buffers (32 rows = 8 chunks of 4 floats)
#define CHK(c, r0) ((((r0) >> 2) ^ ((c) & 7)) << 2)
#define SWI(c, r)  ((c)*32 + CHK(c, r) + ((r) & 3))

// ---- SMEM float offsets ----
#define O_BASE 0
#define O_TZ1  8192
#define O_WE   16384
#define O_POOL 24576     // 32768
#define O_DR   57344
#define O_PB   57376     // 128
#define SMEM_FLOATS 57504
// pool-relative
#define P_A12  0         // 3*8192 (primal); JVP quad 4*8192; OUT3 3*4096 overlay
#define P_CND  24576     // 1536
#define P_Y    26112     // 2048 (phase-1 temp)
#define P_EPS  28160     // 2048 (phase-1 temp)
#define P_W3T  0         // 16640 (phase-1 temp, under A12)

__global__ void precompute_k(const float* __restrict__ cu, const float* __restrict__ cv,
                             const float* __restrict__ W1){
    int c = threadIdx.x;
    float su = 0.f, sv = 0.f;
    #pragma unroll
    for (int j = 0; j < 16; j++){
        float w = __ldg(W1 + (65+j)*256 + c);
        su += __ldg(cu + j) * w;
        sv += __ldg(cv + j) * w;
    }
    g_cd[0][c] = su; g_cd[1][c] = sv;
}

__global__ void __launch_bounds__(TPB, 1) node_main(
    const float* __restrict__ gt, const float* __restrict__ gx, const float* __restrict__ geps,
    const float* __restrict__ gcu, const float* __restrict__ gcv, const float* __restrict__ gcf,
    const float* __restrict__ W1, const float* __restrict__ b1,
    const float* __restrict__ W2, const float* __restrict__ b2,
    const float* __restrict__ W3, const float* __restrict__ b3,
    float* __restrict__ out, int B)
{
    extern __shared__ float sm[];
    const int tid  = threadIdx.x;
    const int lane = tid & 31;
    const int wp   = tid >> 5;
    const int row0 = blockIdx.x * 32;

    // ---- P0 ----
    for (int i = tid; i < 64*32; i += TPB){
        int r = i & 31, d = i >> 5; int gr = row0 + r;
        sm[O_POOL + P_Y   + SWI(d, r)] = (gr < B) ? gx[(size_t)gr*65 + d]  : 0.f;
        sm[O_POOL + P_EPS + SWI(d, r)] = (gr < B) ? geps[(size_t)gr*64 + d] : 0.f;
    }
    for (int i = tid; i < 3*16*32; i += TPB){
        int r = i & 31, j = (i >> 5) & 15, s = i >> 9;
        int gr = row0 + r; int gi = (gr < B) ? gr : 0;
        const float* src = (s == 0) ? gcf : ((s == 1) ? gcu : gcv);
        sm[O_POOL + P_CND + s*512 + SWI(j, r)] = src[(size_t)gi*16 + j];
    }
    for (int i = tid; i < 256*64; i += TPB){
        int k = i >> 6, j = i & 63;
        sm[O_POOL + P_W3T + j*260 + k] = __ldg(W3 + k*128 + j);
    }
    __syncthreads();

    // ---- fillBase (warps 0-7) + WE (warps 8-15) ----
    if (wp < 8){
        int s = wp >> 2, cb = (wp >> 1) & 1, rb = wp & 1;
        int c0 = cb*128 + lane, r0 = rb*16;
        ull acc[8][4];
        #pragma unroll
        for (int i = 0; i < 8; i++){ acc[i][0]=0; acc[i][1]=0; acc[i][2]=0; acc[i][3]=0; }
        const float* act = sm + O_POOL + (s ? P_EPS : P_Y);
        #pragma unroll 4
        for (int k = 0; k < 64; k++){
            float w0 = __ldg(W1 + k*256 + c0),      w1 = __ldg(W1 + k*256 + c0 + 32);
            float w2 = __ldg(W1 + k*256 + c0 + 64), w3 = __ldg(W1 + k*256 + c0 + 96);
            ull wd[4] = {pk(w0,w0), pk(w1,w1), pk(w2,w2), pk(w3,w3)};
            ulonglong2 q0 = *(const ulonglong2*)(act + k*32 + CHK(k, r0));
            ulonglong2 q1 = *(const ulonglong2*)(act + k*32 + CHK(k, r0+4));
            ulonglong2 q2 = *(const ulonglong2*)(act + k*32 + CHK(k, r0+8));
            ulonglong2 q3 = *(const ulonglong2*)(act + k*32 + CHK(k, r0+12));
            ull ar[8] = {q0.x,q0.y,q1.x,q1.y,q2.x,q2.y,q3.x,q3.y};
            #pragma unroll
            for (int rp = 0; rp < 8; rp++)
                #pragma unroll
                for (int j = 0; j < 4; j++) fma2(acc[rp][j], ar[rp], wd[j]);
        }
        float tv = __ldg(gt);
        #pragma unroll
        for (int j = 0; j < 4; j++){
            int c = c0 + 32*j;
            float sft = (s == 0) ? (tv*__ldg(W1 + 64*256 + c) + __ldg(b1 + c)) : 0.f;
            int obuf = (s == 0) ? O_BASE : O_TZ1;
            #pragma unroll
            for (int rp = 0; rp < 8; rp++){
                int r = r0 + 2*rp;
                float lo, hi; upk(acc[rp][j], lo, hi);
                *(float2*)(sm + obuf + c*32 + CHK(c, r) + (r & 3)) = make_float2(lo + sft, hi + sft);
            }
        }
    } else {
        int w8 = wp - 8; int kb = (w8 >> 1)*64 + lane, rb = w8 & 1, r0 = rb*16;
        ull acc[8][2];
        #pragma unroll
        for (int i = 0; i < 8; i++){ acc[i][0]=0; acc[i][1]=0; }
        const float* act = sm + O_POOL + P_EPS;
        #pragma unroll 4
        for (int c = 0; c < 64; c++){
            float w0 = sm[O_POOL + P_W3T + c*260 + kb];
            float w1 = sm[O_POOL + P_W3T + c*260 + kb + 32];
            ull wd[2] = {pk(w0,w0), pk(w1,w1)};
            ulonglong2 q0 = *(const ulonglong2*)(act + c*32 + CHK(c, r0));
            ulonglong2 q1 = *(const ulonglong2*)(act + c*32 + CHK(c, r0+4));
            ulonglong2 q2 = *(const ulonglong2*)(act + c*32 + CHK(c, r0+8));
            ulonglong2 q3 = *(const ulonglong2*)(act + c*32 + CHK(c, r0+12));
            ull ar[8] = {q0.x,q0.y,q1.x,q1.y,q2.x,q2.y,q3.x,q3.y};
            #pragma unroll
            for (int rp = 0; rp < 8; rp++){
                fma2(acc[rp][0], ar[rp], wd[0]);
                fma2(acc[rp][1], ar[rp], wd[1]);
            }
        }
        #pragma unroll
        for (int j = 0; j < 2; j++){
            int k = kb + 32*j;
            #pragma unroll
            for (int rp = 0; rp < 8; rp++){
                int r = r0 + 2*rp;
                float lo, hi; upk(acc[rp][j], lo, hi);
                *(float2*)(sm + O_WE + k*32 + CHK(k, r) + (r & 3)) = make_float2(lo, hi);
            }
        }
    }
    __syncthreads();

    const int sA = wp >> 2, cbA = (wp >> 1) & 1, rbA = wp & 1;
    const int c0A = cbA*128 + lane, r0A = rbA*16;

    // ---- fillA1 (3 conds, K=16) ----
    if (wp < 12){
        ull acc[8][4];
        #pragma unroll
        for (int i = 0; i < 8; i++){ acc[i][0]=0; acc[i][1]=0; acc[i][2]=0; acc[i][3]=0; }
        const float* act = sm + O_POOL + P_CND + sA*512;
        #pragma unroll
        for (int k = 0; k < 16; k++){
            const float* wr = W1 + (65+k)*256 + c0A;
            float w0 = __ldg(wr), w1 = __ldg(wr+32), w2 = __ldg(wr+64), w3 = __ldg(wr+96);
            ull wd[4] = {pk(w0,w0), pk(w1,w1), pk(w2,w2), pk(w3,w3)};
            ulonglong2 q0 = *(const ulonglong2*)(act + k*32 + CHK(k, r0A));
            ulonglong2 q1 = *(const ulonglong2*)(act + k*32 + CHK(k, r0A+4));
            ulonglong2 q2 = *(const ulonglong2*)(act + k*32 + CHK(k, r0A+8));
            ulonglong2 q3 = *(const ulonglong2*)(act + k*32 + CHK(k, r0A+12));
            ull ar[8] = {q0.x,q0.y,q1.x,q1.y,q2.x,q2.y,q3.x,q3.y};
            #pragma unroll
            for (int rp = 0; rp < 8; rp++)
                #pragma unroll
                for (int j = 0; j < 4; j++) fma2(acc[rp][j], ar[rp], wd[j]);
        }
        #pragma unroll
        for (int j = 0; j < 4; j++){
            int c = c0A + 32*j;
            #pragma unroll
            for (int rp = 0; rp < 8; rp++){
                int r = r0A + 2*rp;
                float lo, hi; upk(acc[rp][j], lo, hi);
                float2 b = *(const float2*)(sm + O_BASE + c*32 + CHK(c, r) + (r & 3));
                *(float2*)(sm + O_POOL + P_A12 + sA*8192 + c*32 + CHK(c, r) + (r & 3)) =
                    make_float2(siluf(lo + b.x), siluf(hi + b.y));
            }
        }
    }
    __syncthreads();

    // ---- layer2 primal (in-place A12, direct LDG W2) ----
    {
        ull acc[8][4];
        #pragma unroll
        for (int i = 0; i < 8; i++){ acc[i][0]=0; acc[i][1]=0; acc[i][2]=0; acc[i][3]=0; }
        if (wp < 12){
            const float* act = sm + O_POOL + P_A12 + sA*8192;
            #pragma unroll 4
            for (int k = 0; k < 256; k++){
                const float* wr = W2 + k*256 + c0A;
                float w0 = __ldg(wr), w1 = __ldg(wr+32), w2 = __ldg(wr+64), w3 = __ldg(wr+96);
                ull wd[4] = {pk(w0,w0), pk(w1,w1), pk(w2,w2), pk(w3,w3)};
                ulonglong2 q0 = *(const ulonglong2*)(act + k*32 + CHK(k, r0A));
                ulonglong2 q1 = *(const ulonglong2*)(act + k*32 + CHK(k, r0A+4));
                ulonglong2 q2 = *(const ulonglong2*)(act + k*32 + CHK(k, r0A+8));
                ulonglong2 q3 = *(const ulonglong2*)(act + k*32 + CHK(k, r0A+12));
                ull ar[8] = {q0.x,q0.y,q1.x,q1.y,q2.x,q2.y,q3.x,q3.y};
                #pragma unroll
                for (int rp = 0; rp < 8; rp++)
                    #pragma unroll
                    for (int j = 0; j < 4; j++) fma2(acc[rp][j], ar[rp], wd[j]);
            }
        }
        __syncthreads();   // all k-loop reads complete before in-place writes
        if (wp < 12){
            #pragma unroll
            for (int j = 0; j < 4; j++){
                int c = c0A + 32*j;
                float bb = __ldg(b2 + c);
                #pragma unroll
                for (int rp = 0; rp < 8; rp++){
                    int r = r0A + 2*rp;
                    float lo, hi; upk(acc[rp][j], lo, hi);
                    *(float2*)(sm + O_POOL + P_A12 + sA*8192 + c*32 + CHK(c, r) + (r & 3)) =
                        make_float2(siluf(lo + bb), siluf(hi + bb));
                }
            }
        }
    }
    __syncthreads();

    // ---- layer3 primal (128 cols) -> OUT3 overlay ----
    {
        ull acc[8][2];
        #pragma unroll
        for (int i = 0; i < 8; i++){ acc[i][0]=0; acc[i][1]=0; }
        int c03 = cbA*64 + lane;
        if (wp < 12){
            const float* act = sm + O_POOL + P_A12 + sA*8192;
            #pragma unroll 4
            for (int k = 0; k < 256; k++){
                float w0 = __ldg(W3 + k*128 + c03), w1 = __ldg(W3 + k*128 + c03 + 32);
                ull wd[2] = {pk(w0,w0), pk(w1,w1)};
                ulonglong2 q0 = *(const ulonglong2*)(act + k*32 + CHK(k, r0A));
                ulonglong2 q1 = *(const ulonglong2*)(act + k*32 + CHK(k, r0A+4));
                ulonglong2 q2 = *(const ulonglong2*)(act + k*32 + CHK(k, r0A+8));
                ulonglong2 q3 = *(const ulonglong2*)(act + k*32 + CHK(k, r0A+12));
                ull ar[8] = {q0.x,q0.y,q1.x,q1.y,q2.x,q2.y,q3.x,q3.y};
                #pragma unroll
                for (int rp = 0; rp < 8; rp++){
                    fma2(acc[rp][0], ar[rp], wd[0]);
                    fma2(acc[rp][1], ar[rp], wd[1]);
                }
            }
        }
        __syncthreads();   // OUT3 overlays A12 — all reads must complete first
        if (wp < 12){
            #pragma unroll
            for (int j = 0; j < 2; j++){
                int c = c03 + 32*j;
                float bb = __ldg(b3 + c);
                #pragma unroll
                for (int rp = 0; rp < 8; rp++){
                    int r = r0A + 2*rp;
                    float lo, hi; upk(acc[rp][j], lo, hi);
                    *(float2*)(sm + O_POOL + sA*4096 + c*32 + CHK(c, r) + (r & 3)) =
                        make_float2(lo + bb, hi + bb);
                }
            }
        }
    }
    __syncthreads();

    // ---- ft output + corrections ----
    {
        int cc = tid & 15, r = tid >> 4;
        int gr = row0 + r;
        float part = 0.f;
        #pragma unroll
        for (int j = 0; j < 4; j++){
            int c = cc + 16*j;
            float fv = sm[O_POOL + 0*4096 + SWI(c, r)];
            float uv = sm[O_POOL + 1*4096 + SWI(c, r)];
            float vv = sm[O_POOL + 2*4096 + SWI(c, r)];
            float su = sm[O_POOL + 1*4096 + SWI(c + 64, r)];
            float sv = sm[O_POOL + 2*4096 + SWI(c + 64, r)];
            part += (fv - uv)*su - (fv - vv)*sv;
            if (gr < B) out[(size_t)gr*65 + c] = fv;
        }
        part += __shfl_down_sync(0xffffffffu, part, 8, 16);
        part += __shfl_down_sync(0xffffffffu, part, 4, 16);
        part += __shfl_down_sync(0xffffffffu, part, 2, 16);
        part += __shfl_down_sync(0xffffffffu, part, 1, 16);
        if ((tid & 15) == 0) sm[O_DR + r] = part;
    }
    __syncthreads();

    // ---- fillJ: quad streams {pu, tu, pv, tv} ----
    #pragma unroll 4
    for (int ci = 0; ci < 16; ci++){
        int c = wp*16 + ci;
        float bs = sm[O_BASE + SWI(c, lane)];
        float tz = sm[O_TZ1  + SWI(c, lane)];
        float zu = bs + g_cd[0][c], zv = bs + g_cd[1][c];
        sm[O_POOL + 0*8192 + SWI(c, lane)] = siluf(zu);
        sm[O_POOL + 1*8192 + SWI(c, lane)] = dsiluf(zu)*tz;
        sm[O_POOL + 2*8192 + SWI(c, lane)] = siluf(zv);
        sm[O_POOL + 3*8192 + SWI(c, lane)] = dsiluf(zv)*tz;
    }
    __syncthreads();

    // ---- JVP layer2 (16 warps) + fused WE-dot epilogue ----
    {
        ull acc[8][4];
        #pragma unroll
        for (int i = 0; i < 8; i++){ acc[i][0]=0; acc[i][1]=0; acc[i][2]=0; acc[i][3]=0; }
        const float* act = sm + O_POOL + sA*8192;
        #pragma unroll 4
        for (int k = 0; k < 256; k++){
            const float* wr = W2 + k*256 + c0A;
            float w0 = __ldg(wr), w1 = __ldg(wr+32), w2 = __ldg(wr+64), w3 = __ldg(wr+96);
            ull wd[4] = {pk(w0,w0), pk(w1,w1), pk(w2,w2), pk(w3,w3)};
            ulonglong2 q0 = *(const ulonglong2*)(act + k*32 + CHK(k, r0A));
            ulonglong2 q1 = *(const ulonglong2*)(act + k*32 + CHK(k, r0A+4));
            ulonglong2 q2 = *(const ulonglong2*)(act + k*32 + CHK(k, r0A+8));
            ulonglong2 q3 = *(const ulonglong2*)(act + k*32 + CHK(k, r0A+12));
            ull ar[8] = {q0.x,q0.y,q1.x,q1.y,q2.x,q2.y,q3.x,q3.y};
            #pragma unroll
            for (int rp = 0; rp < 8; rp++)
                #pragma unroll
                for (int j = 0; j < 4; j++) fma2(acc[rp][j], ar[rp], wd[j]);
        }
        __syncthreads();   // all reads complete before z2 staging overlays
        if ((sA & 1) == 0){
            #pragma unroll
            for (int j = 0; j < 4; j++){
                int c = c0A + 32*j;
                #pragma unroll
                for (int rp = 0; rp < 8; rp++){
                    int r = r0A + 2*rp;
                    float lo, hi; upk(acc[rp][j], lo, hi);
                    *(float2*)(sm + O_POOL + sA*8192 + c*32 + CHK(c, r) + (r & 3)) = make_float2(lo, hi);
                }
            }
        }
        __syncthreads();
        if (sA & 1){
            float prow[16];
            #pragma unroll
            for (int i = 0; i < 16; i++) prow[i] = 0.f;
            #pragma unroll
            for (int j = 0; j < 4; j++){
                int c = c0A + 32*j;
                float bb = __ldg(b2 + c);
                #pragma unroll
                for (int rp = 0; rp < 8; rp++){
                    int r = r0A + 2*rp;
                    float2 z  = *(const float2*)(sm + O_POOL + (sA-1)*8192 + c*32 + CHK(c, r) + (r & 3));
                    float2 we = *(const float2*)(sm + O_WE + c*32 + CHK(c, r) + (r & 3));
                    float t0, t1; upk(acc[rp][j], t0, t1);
                    prow[2*rp]   += dsiluf(z.x + bb) * t0 * we.x;
                    prow[2*rp+1] += dsiluf(z.y + bb) * t1 * we.y;
                }
            }
            #pragma unroll
            for (int off = 16; off >= 1; off >>= 1)
                #pragma unroll
                for (int i = 0; i < 16; i++)
                    prow[i] += __shfl_down_sync(0xffffffffu, prow[i], off);
            if (lane == 0){
                int q = (sA >> 1)*2 + cbA;
                #pragma unroll
                for (int i = 0; i < 16; i++) sm[O_PB + q*32 + r0A + i] = prow[i];
            }
        }
    }
    __syncthreads();

    // ---- finalize: dr = corr - e.(Ju e) + e.(Jv e) ----
    if (tid < 32){
        float dr = sm[O_DR + tid]
                 - (sm[O_PB + tid] + sm[O_PB + 32 + tid])
                 + (sm[O_PB + 64 + tid] + sm[O_PB + 96 + tid]);
        int gr = row0 + tid;
        if (gr < B) out[(size_t)gr*65 + 64] = dr;
    }
}

extern "C" void kernel_launch(void* const* d_in, const int* in_sizes, int n_in,
                              void* d_out, int out_size)
{
    const float* gt  = (const float*)d_in[0];
    const float* gx  = (const float*)d_in[1];
    const float* ge  = (const float*)d_in[2];
    const float* gcu = (const float*)d_in[3];
    const float* gcv = (const float*)d_in[4];
    const float* gcf = (const float*)d_in[5];
    const float* W1  = (const float*)d_in[6];
    const float* b1  = (const float*)d_in[7];
    const float* W2  = (const float*)d_in[8];
    const float* b2  = (const float*)d_in[9];
    const float* W3  = (const float*)d_in[10];
    const float* b3  = (const float*)d_in[11];
    float* out = (float*)d_out;

    int B = in_sizes[1] / 65;
    int grid = (B + 31) / 32;

    cudaFuncSetAttribute(node_main, cudaFuncAttributeMaxDynamicSharedMemorySize, SMEM_FLOATS*4);

    precompute_k<<<1, 256>>>(gcu, gcv, W1);
    node_main<<<grid, TPB, SMEM_FLOATS*4>>>(gt, gx, ge, gcu, gcv, gcf,
                                            W1, b1, W2, b2, W3, b3, out, B);
}

// round 12
// speedup vs baseline: 1.0013x; 1.0004x over previous
#include <cuda_runtime.h>
#define TPB 512
typedef unsigned long long ull;

static __device__ __forceinline__ ull pk(float lo, float hi){ ull r; asm("mov.b64 %0,{%1,%2};":"=l"(r):"f"(lo),"f"(hi)); return r; }
static __device__ __forceinline__ void upk(ull v, float &lo, float &hi){ asm("mov.b64 {%0,%1},%2;":"=f"(lo),"=f"(hi):"l"(v)); }
static __device__ __forceinline__ void fma2(ull &d, ull a, ull b){ asm("fma.rn.f32x2 %0,%1,%2,%0;":"+l"(d):"l"(a),"l"(b)); }
static __device__ __forceinline__ float siluf(float z){ return z*(1.f/(1.f+__expf(-z))); }
static __device__ __forceinline__ float dsiluf(float z){ float s=1.f/(1.f+__expf(-z)); return s*(1.f+z*(1.f-s)); }

__device__ float g_cd[2][256];

// XOR-16B-chunk swizzle for [col][row] buffers (32 rows = 8 chunks of 4 floats)
#define CHK(c, r0) ((((r0) >> 2) ^ ((c) & 7)) << 2)
#define SWI(c, r)  ((c)*32 + CHK(c, r) + ((r) & 3))

// ---- SMEM float offsets ----
#define O_BASE 0
#define O_TZ1  8192
#define O_WE   16384
#define O_POOL 24576     // 32768
#define O_DR   57344
#define O_PB   57376     // 128
#define SMEM_FLOATS 57504
// pool-relative
#define P_A12  0         // 3*8192 (primal); JVP quad 4*8192; OUT3 3*4096 overlay
#define P_CND  24576     // 1536
#define P_Y    26112     // 2048 (phase-1 temp)
#define P_EPS  28160     // 2048 (phase-1 temp)
#define P_W3T  0         // 16640 (phase-1 temp, under A12)

__global__ void precompute_k(const float* __restrict__ cu, const float* __restrict__ cv,
                             const float* __restrict__ W1){
    int c = threadIdx.x;
    float su = 0.f, sv = 0.f;
    #pragma unroll
    for (int j = 0; j < 16; j++){
        float w = __ldg(W1 + (65+j)*256 + c);
        su += __ldg(cu + j) * w;
        sv += __ldg(cv + j) * w;
    }
    g_cd[0][c] = su; g_cd[1][c] = sv;
}

__global__ void __launch_bounds__(TPB, 1) node_main(
    const float* __restrict__ gt, const float* __restrict__ gx, const float* __restrict__ geps,
    const float* __restrict__ gcu, const float* __restrict__ gcv, const float* __restrict__ gcf,
    const float* __restrict__ W1, const float* __restrict__ b1,
    const float* __restrict__ W2, const float* __restrict__ b2,
    const float* __restrict__ W3, const float* __restrict__ b3,
    float* __restrict__ out, int B)
{
    extern __shared__ float sm[];
    const int tid  = threadIdx.x;
    const int lane = tid & 31;
    const int wp   = tid >> 5;
    const int row0 = blockIdx.x * 32;

    // ---- P0 ----
    for (int i = tid; i < 64*32; i += TPB){
        int r = i & 31, d = i >> 5; int gr = row0 + r;
        sm[O_POOL + P_Y   + SWI(d, r)] = (gr < B) ? gx[(size_t)gr*65 + d]  : 0.f;
        sm[O_POOL + P_EPS + SWI(d, r)] = (gr < B) ? geps[(size_t)gr*64 + d] : 0.f;
    }
    for (int i = tid; i < 3*16*32; i += TPB){
        int r = i & 31, j = (i >> 5) & 15, s = i >> 9;
        int gr = row0 + r; int gi = (gr < B) ? gr : 0;
        const float* src = (s == 0) ? gcf : ((s == 1) ? gcu : gcv);
        sm[O_POOL + P_CND + s*512 + SWI(j, r)] = src[(size_t)gi*16 + j];
    }
    for (int i = tid; i < 256*64; i += TPB){
        int k = i >> 6, j = i & 63;
        sm[O_POOL + P_W3T + j*260 + k] = __ldg(W3 + k*128 + j);
    }
    __syncthreads();

    // ---- fillBase (warps 0-7) + WE (warps 8-15) ----
    if (wp < 8){
        int s = wp >> 2, cb = (wp >> 1) & 1, rb = wp & 1;
        int c0 = cb*128 + lane, r0 = rb*16;
        ull acc[8][4];
        #pragma unroll
        for (int i = 0; i < 8; i++){ acc[i][0]=0; acc[i][1]=0; acc[i][2]=0; acc[i][3]=0; }
        const float* act = sm + O_POOL + (s ? P_EPS : P_Y);
        #pragma unroll 4
        for (int k = 0; k < 64; k++){
            float w0 = __ldg(W1 + k*256 + c0),      w1 = __ldg(W1 + k*256 + c0 + 32);
            float w2 = __ldg(W1 + k*256 + c0 + 64), w3 = __ldg(W1 + k*256 + c0 + 96);
            ull wd[4] = {pk(w0,w0), pk(w1,w1), pk(w2,w2), pk(w3,w3)};
            ulonglong2 q0 = *(const ulonglong2*)(act + k*32 + CHK(k, r0));
            ulonglong2 q1 = *(const ulonglong2*)(act + k*32 + CHK(k, r0+4));
            ulonglong2 q2 = *(const ulonglong2*)(act + k*32 + CHK(k, r0+8));
            ulonglong2 q3 = *(const ulonglong2*)(act + k*32 + CHK(k, r0+12));
            ull ar[8] = {q0.x,q0.y,q1.x,q1.y,q2.x,q2.y,q3.x,q3.y};
            #pragma unroll
            for (int rp = 0; rp < 8; rp++)
                #pragma unroll
                for (int j = 0; j < 4; j++) fma2(acc[rp][j], ar[rp], wd[j]);
        }
        float tv = __ldg(gt);
        #pragma unroll
        for (int j = 0; j < 4; j++){
            int c = c0 + 32*j;
            float sft = (s == 0) ? (tv*__ldg(W1 + 64*256 + c) + __ldg(b1 + c)) : 0.f;
            int obuf = (s == 0) ? O_BASE : O_TZ1;
            #pragma unroll
            for (int rp = 0; rp < 8; rp++){
                int r = r0 + 2*rp;
                float lo, hi; upk(acc[rp][j], lo, hi);
                *(float2*)(sm + obuf + c*32 + CHK(c, r) + (r & 3)) = make_float2(lo + sft, hi + sft);
            }
        }
    } else {
        int w8 = wp - 8; int kb = (w8 >> 1)*64 + lane, rb = w8 & 1, r0 = rb*16;
        ull acc[8][2];
        #pragma unroll
        for (int i = 0; i < 8; i++){ acc[i][0]=0; acc[i][1]=0; }
        const float* act = sm + O_POOL + P_EPS;
        #pragma unroll 4
        for (int c = 0; c < 64; c++){
            float w0 = sm[O_POOL + P_W3T + c*260 + kb];
            float w1 = sm[O_POOL + P_W3T + c*260 + kb + 32];
            ull wd[2] = {pk(w0,w0), pk(w1,w1)};
            ulonglong2 q0 = *(const ulonglong2*)(act + c*32 + CHK(c, r0));
            ulonglong2 q1 = *(const ulonglong2*)(act + c*32 + CHK(c, r0+4));
            ulonglong2 q2 = *(const ulonglong2*)(act + c*32 + CHK(c, r0+8));
            ulonglong2 q3 = *(const ulonglong2*)(act + c*32 + CHK(c, r0+12));
            ull ar[8] = {q0.x,q0.y,q1.x,q1.y,q2.x,q2.y,q3.x,q3.y};
            #pragma unroll
            for (int rp = 0; rp < 8; rp++){
                fma2(acc[rp][0], ar[rp], wd[0]);
                fma2(acc[rp][1], ar[rp], wd[1]);
            }
        }
        #pragma unroll
        for (int j = 0; j < 2; j++){
            int k = kb + 32*j;
            #pragma unroll
            for (int rp = 0; rp < 8; rp++){
                int r = r0 + 2*rp;
                float lo, hi; upk(acc[rp][j], lo, hi);
                *(float2*)(sm + O_WE + k*32 + CHK(k, r) + (r & 3)) = make_float2(lo, hi);
            }
        }
    }
    __syncthreads();

    const int sA = wp >> 2, cbA = (wp >> 1) & 1, rbA = wp & 1;
    const int c0A = cbA*128 + lane, r0A = rbA*16;

    // ---- fillA1 (3 conds, K=16) ----
    if (wp < 12){
        ull acc[8][4];
        #pragma unroll
        for (int i = 0; i < 8; i++){ acc[i][0]=0; acc[i][1]=0; acc[i][2]=0; acc[i][3]=0; }
        const float* act = sm + O_POOL + P_CND + sA*512;
        #pragma unroll
        for (int k = 0; k < 16; k++){
            const float* wr = W1 + (65+k)*256 + c0A;
            float w0 = __ldg(wr), w1 = __ldg(wr+32), w2 = __ldg(wr+64), w3 = __ldg(wr+96);
            ull wd[4] = {pk(w0,w0), pk(w1,w1), pk(w2,w2), pk(w3,w3)};
            ulonglong2 q0 = *(const ulonglong2*)(act + k*32 + CHK(k, r0A));
            ulonglong2 q1 = *(const ulonglong2*)(act + k*32 + CHK(k, r0A+4));
            ulonglong2 q2 = *(const ulonglong2*)(act + k*32 + CHK(k, r0A+8));
            ulonglong2 q3 = *(const ulonglong2*)(act + k*32 + CHK(k, r0A+12));
            ull ar[8] = {q0.x,q0.y,q1.x,q1.y,q2.x,q2.y,q3.x,q3.y};
            #pragma unroll
            for (int rp = 0; rp < 8; rp++)
                #pragma unroll
                for (int j = 0; j < 4; j++) fma2(acc[rp][j], ar[rp], wd[j]);
        }
        #pragma unroll
        for (int j = 0; j < 4; j++){
            int c = c0A + 32*j;
            #pragma unroll
            for (int rp = 0; rp < 8; rp++){
                int r = r0A + 2*rp;
                float lo, hi; upk(acc[rp][j], lo, hi);
                float2 b = *(const float2*)(sm + O_BASE + c*32 + CHK(c, r) + (r & 3));
                *(float2*)(sm + O_POOL + P_A12 + sA*8192 + c*32 + CHK(c, r) + (r & 3)) =
                    make_float2(siluf(lo + b.x), siluf(hi + b.y));
            }
        }
    }
    __syncthreads();

    // ---- layer2 primal (in-place A12, direct LDG W2) ----
    {
        ull acc[8][4];
        #pragma unroll
        for (int i = 0; i < 8; i++){ acc[i][0]=0; acc[i][1]=0; acc[i][2]=0; acc[i][3]=0; }
        if (wp < 12){
            const float* act = sm + O_POOL + P_A12 + sA*8192;
            #pragma unroll 4
            for (int k = 0; k < 256; k++){
                const float* wr = W2 + k*256 + c0A;
                float w0 = __ldg(wr), w1 = __ldg(wr+32), w2 = __ldg(wr+64), w3 = __ldg(wr+96);
                ull wd[4] = {pk(w0,w0), pk(w1,w1), pk(w2,w2), pk(w3,w3)};
                ulonglong2 q0 = *(const ulonglong2*)(act + k*32 + CHK(k, r0A));
                ulonglong2 q1 = *(const ulonglong2*)(act + k*32 + CHK(k, r0A+4));
                ulonglong2 q2 = *(const ulonglong2*)(act + k*32 + CHK(k, r0A+8));
                ulonglong2 q3 = *(const ulonglong2*)(act + k*32 + CHK(k, r0A+12));
                ull ar[8] = {q0.x,q0.y,q1.x,q1.y,q2.x,q2.y,q3.x,q3.y};
                #pragma unroll
                for (int rp = 0; rp < 8; rp++)
                    #pragma unroll
                    for (int j = 0; j < 4; j++) fma2(acc[rp][j], ar[rp], wd[j]);
            }
        }
        __syncthreads();   // all k-loop reads complete before in-place writes
        if (wp < 12){
            #pragma unroll
            for (int j = 0; j < 4; j++){
                int c = c0A + 32*j;
                float bb = __ldg(b2 + c);
                #pragma unroll
                for (int rp = 0; rp < 8; rp++){
                    int r = r0A + 2*rp;
                    float lo, hi; upk(acc[rp][j], lo, hi);
                    *(float2*)(sm + O_POOL + P_A12 + sA*8192 + c*32 + CHK(c, r) + (r & 3)) =
                        make_float2(siluf(lo + bb), siluf(hi + bb));
                }
            }
        }
    }
    __syncthreads();

    // ---- layer3 primal (128 cols) -> OUT3 overlay ----
    {
        ull acc[8][2];
        #pragma unroll
        for (int i = 0; i < 8; i++){ acc[i][0]=0; acc[i][1]=0; }
        int c03 = cbA*64 + lane;
        if (wp < 12){
            const float* act = sm + O_POOL + P_A12 + sA*8192;
            #pragma unroll 4
            for (int k = 0; k < 256; k++){
                float w0 = __ldg(W3 + k*128 + c03), w1 = __ldg(W3 + k*128 + c03 + 32);
                ull wd[2] = {pk(w0,w0), pk(w1,w1)};
                ulonglong2 q0 = *(const ulonglong2*)(act + k*32 + CHK(k, r0A));
                ulonglong2 q1 = *(const ulonglong2*)(act + k*32 + CHK(k, r0A+4));
                ulonglong2 q2 = *(const ulonglong2*)(act + k*32 + CHK(k, r0A+8));
                ulonglong2 q3 = *(const ulonglong2*)(act + k*32 + CHK(k, r0A+12));
                ull ar[8] = {q0.x,q0.y,q1.x,q1.y,q2.x,q2.y,q3.x,q3.y};
                #pragma unroll
                for (int rp = 0; rp < 8; rp++){
                    fma2(acc[rp][0], ar[rp], wd[0]);
                    fma2(acc[rp][1], ar[rp], wd[1]);
                }
            }
        }
        __syncthreads();   // OUT3 overlays A12 — all reads must complete first
        if (wp < 12){
            #pragma unroll
            for (int j = 0; j < 2; j++){
                int c = c03 + 32*j;
                float bb = __ldg(b3 + c);
                #pragma unroll
                for (int rp = 0; rp < 8; rp++){
                    int r = r0A + 2*rp;
                    float lo, hi; upk(acc[rp][j], lo, hi);
                    *(float2*)(sm + O_POOL + sA*4096 + c*32 + CHK(c, r) + (r & 3)) =
                        make_float2(lo + bb, hi + bb);
                }
            }
        }
    }
    __syncthreads();

    // ---- ft output + corrections ----
    {
        int cc = tid & 15, r = tid >> 4;
        int gr = row0 + r;
        float part = 0.f;
        #pragma unroll
        for (int j = 0; j < 4; j++){
            int c = cc + 16*j;
            float fv = sm[O_POOL + 0*4096 + SWI(c, r)];
            float uv = sm[O_POOL + 1*4096 + SWI(c, r)];
            float vv = sm[O_POOL + 2*4096 + SWI(c, r)];
            float su = sm[O_POOL + 1*4096 + SWI(c + 64, r)];
            float sv = sm[O_POOL + 2*4096 + SWI(c + 64, r)];
            part += (fv - uv)*su - (fv - vv)*sv;
            if (gr < B) out[(size_t)gr*65 + c] = fv;
        }
        part += __shfl_down_sync(0xffffffffu, part, 8, 16);
        part += __shfl_down_sync(0xffffffffu, part, 4, 16);
        part += __shfl_down_sync(0xffffffffu, part, 2, 16);
        part += __shfl_down_sync(0xffffffffu, part, 1, 16);
        if ((tid & 15) == 0) sm[O_DR + r] = part;
    }
    __syncthreads();

    // ---- fillJ: quad streams {pu, tu, pv, tv} ----
    #pragma unroll 4
    for (int ci = 0; ci < 16; ci++){
        int c = wp*16 + ci;
        float bs = sm[O_BASE + SWI(c, lane)];
        float tz = sm[O_TZ1  + SWI(c, lane)];
        float zu = bs + g_cd[0][c], zv = bs + g_cd[1][c];
        sm[O_POOL + 0*8192 + SWI(c, lane)] = siluf(zu);
        sm[O_POOL + 1*8192 + SWI(c, lane)] = dsiluf(zu)*tz;
        sm[O_POOL + 2*8192 + SWI(c, lane)] = siluf(zv);
        sm[O_POOL + 3*8192 + SWI(c, lane)] = dsiluf(zv)*tz;
    }
    __syncthreads();

    // ---- JVP layer2 (16 warps) + fused WE-dot epilogue ----
    {
        ull acc[8][4];
        #pragma unroll
        for (int i = 0; i < 8; i++){ acc[i][0]=0; acc[i][1]=0; acc[i][2]=0; acc[i][3]=0; }
        const float* act = sm + O_POOL + sA*8192;
        #pragma unroll 4
        for (int k = 0; k < 256; k++){
            const float* wr = W2 + k*256 + c0A;
            float w0 = __ldg(wr), w1 = __ldg(wr+32), w2 = __ldg(wr+64), w3 = __ldg(wr+96);
            ull wd[4] = {pk(w0,w0), pk(w1,w1), pk(w2,w2), pk(w3,w3)};
            ulonglong2 q0 = *(const ulonglong2*)(act + k*32 + CHK(k, r0A));
            ulonglong2 q1 = *(const ulonglong2*)(act + k*32 + CHK(k, r0A+4));
            ulonglong2 q2 = *(const ulonglong2*)(act + k*32 + CHK(k, r0A+8));
            ulonglong2 q3 = *(const ulonglong2*)(act + k*32 + CHK(k, r0A+12));
            ull ar[8] = {q0.x,q0.y,q1.x,q1.y,q2.x,q2.y,q3.x,q3.y};
            #pragma unroll
            for (int rp = 0; rp < 8; rp++)
                #pragma unroll
                for (int j = 0; j < 4; j++) fma2(acc[rp][j], ar[rp], wd[j]);
        }
        __syncthreads();   // all reads complete before z2 staging overlays
        if ((sA & 1) == 0){
            #pragma unroll
            for (int j = 0; j < 4; j++){
                int c = c0A + 32*j;
                #pragma unroll
                for (int rp = 0; rp < 8; rp++){
                    int r = r0A + 2*rp;
                    float lo, hi; upk(acc[rp][j], lo, hi);
                    *(float2*)(sm + O_POOL + sA*8192 + c*32 + CHK(c, r) + (r & 3)) = make_float2(lo, hi);
                }
            }
        }
        __syncthreads();
        if (sA & 1){
            float prow[16];
            #pragma unroll
            for (int i = 0; i < 16; i++) prow[i] = 0.f;
            #pragma unroll
            for (int j = 0; j < 4; j++){
                int c = c0A + 32*j;
                float bb = __ldg(b2 + c);
                #pragma unroll
                for (int rp = 0; rp < 8; rp++){
                    int r = r0A + 2*rp;
                    float2 z  = *(const float2*)(sm + O_POOL + (sA-1)*8192 + c*32 + CHK(c, r) + (r & 3));
                    float2 we = *(const float2*)(sm + O_WE + c*32 + CHK(c, r) + (r & 3));
                    float t0, t1; upk(acc[rp][j], t0, t1);
                    prow[2*rp]   += dsiluf(z.x + bb) * t0 * we.x;
                    prow[2*rp+1] += dsiluf(z.y + bb) * t1 * we.y;
                }
            }
            #pragma unroll
            for (int off = 16; off >= 1; off >>= 1)
                #pragma unroll
                for (int i = 0; i < 16; i++)
                    prow[i] += __shfl_down_sync(0xffffffffu, prow[i], off);
            if (lane == 0){
                int q = (sA >> 1)*2 + cbA;
                #pragma unroll
                for (int i = 0; i < 16; i++) sm[O_PB + q*32 + r0A + i] = prow[i];
            }
        }
    }
    __syncthreads();

    // ---- finalize: dr = corr - e.(Ju e) + e.(Jv e) ----
    if (tid < 32){
        float dr = sm[O_DR + tid]
                 - (sm[O_PB + tid] + sm[O_PB + 32 + tid])
                 + (sm[O_PB + 64 + tid] + sm[O_PB + 96 + tid]);
        int gr = row0 + tid;
        if (gr < B) out[(size_t)gr*65 + 64] = dr;
    }
}

extern "C" void kernel_launch(void* const* d_in, const int* in_sizes, int n_in,
                              void* d_out, int out_size)
{
    const float* gt  = (const float*)d_in[0];
    const float* gx  = (const float*)d_in[1];
    const float* ge  = (const float*)d_in[2];
    const float* gcu = (const float*)d_in[3];
    const float* gcv = (const float*)d_in[4];
    const float* gcf = (const float*)d_in[5];
    const float* W1  = (const float*)d_in[6];
    const float* b1  = (const float*)d_in[7];
    const float* W2  = (const float*)d_in[8];
    const float* b2  = (const float*)d_in[9];
    const float* W3  = (const float*)d_in[10];
    const float* b3  = (const float*)d_in[11];
    float* out = (float*)d_out;

    int B = in_sizes[1] / 65;
    int grid = (B + 31) / 32;

    cudaFuncSetAttribute(node_main, cudaFuncAttributeMaxDynamicSharedMemorySize, SMEM_FLOATS*4);

    precompute_k<<<1, 256>>>(gcu, gcv, W1);
    node_main<<<grid, TPB, SMEM_FLOATS*4>>>(gt, gx, ge, gcu, gcv, gcf,
                                            W1, b1, W2, b2, W3, b3, out, B);
}